// round 4
// baseline (speedup 1.0000x reference)
#include <cuda_runtime.h>

// DCN cross layer, L=3, D=1024, B=16384 — algebraic form + register-resident W.
//   cross_l = alpha_l * x + (partial bias sums)  =>
//   a_l  = dot(x, W_l)   (3 independent dots, one fused reduction)
//   d_ml = dot(bias_m, W_l) (batch-independent, once per CTA)
//   alpha recurrence (scalars), out = alpha*x + (b0+b1+b2)
// Layout: thread t owns columns [4t,4t+4). W (12 floats) + bias sum (4 floats)
// live in registers for the whole CTA. Per row: ONE __syncthreads (double-
// buffered 8x3 partial scratch), smem traffic ~200B/row vs 12KB in R3.

static constexpr int D  = 1024;
static constexpr int F4 = D / 4;            // 256 float4 per row
static constexpr int THREADS = 256;
static constexpr int NWARP = THREADS / 32;  // 8
static constexpr int R = 16;                // rows per CTA

__device__ __forceinline__ float dot4(float4 a, float4 b) {
    return fmaf(a.x, b.x, fmaf(a.y, b.y, fmaf(a.z, b.z, a.w * b.w)));
}
__device__ __forceinline__ float wred(float v) {
#pragma unroll
    for (int o = 16; o > 0; o >>= 1)
        v += __shfl_xor_sync(0xffffffffu, v, o);
    return v;
}

__global__ __launch_bounds__(THREADS)
void cross_layer_kernel(const float* __restrict__ x,
                        const float* __restrict__ W,
                        const float* __restrict__ bias,
                        float* __restrict__ out)
{
    __shared__ float red[2][NWARP][3];      // double-buffered partials

    const int t    = threadIdx.x;
    const int warp = t >> 5;
    const int lane = t & 31;

    // ---- per-CTA prologue: W/bias to registers, d-constants ----
    const float4* W4 = reinterpret_cast<const float4*>(W);
    const float4* B4 = reinterpret_cast<const float4*>(bias);
    float4 w0 = W4[t], w1 = W4[F4 + t], w2 = W4[2 * F4 + t];
    float4 b0 = B4[t], b1 = B4[F4 + t], b2 = B4[2 * F4 + t];
    float4 bsum;
    bsum.x = b0.x + b1.x + b2.x;  bsum.y = b0.y + b1.y + b2.y;
    bsum.z = b0.z + b1.z + b2.z;  bsum.w = b0.w + b1.w + b2.w;

    float p01 = wred(dot4(b0, w1));
    float p02 = wred(dot4(b0, w2));
    float p12 = wred(dot4(b1, w2));
    if (lane == 0) {
        red[0][warp][0] = p01; red[0][warp][1] = p02; red[0][warp][2] = p12;
    }
    __syncthreads();
    float d01 = 0.f, d2 = 0.f;
#pragma unroll
    for (int w = 0; w < NWARP; w++) {
        d01 += red[0][w][0];
        d2  += red[0][w][1] + red[0][w][2];   // d02 + d12
    }
    __syncthreads();                           // red[0] reused in row loop

    // ---- row loop: one barrier per row ----
    const size_t row0 = (size_t)blockIdx.x * R;
    const float4* xp = reinterpret_cast<const float4*>(x) + row0 * F4 + t;
    float4*       op = reinterpret_cast<float4*>(out)     + row0 * F4 + t;

    float4 xv = __ldcs(xp);

#pragma unroll
    for (int r = 0; r < R; r++) {
        // partial dots against register-resident W
        float pa0 = dot4(xv, w0);
        float pa1 = dot4(xv, w1);
        float pa2 = dot4(xv, w2);

        // prefetch next row's x (hides under the reduction)
        float4 xnext;
        if (r + 1 < R) xnext = __ldcs(xp + (size_t)(r + 1) * F4);

        pa0 = wred(pa0); pa1 = wred(pa1); pa2 = wred(pa2);
        const int buf = r & 1;
        if (lane == 0) {
            red[buf][warp][0] = pa0;
            red[buf][warp][1] = pa1;
            red[buf][warp][2] = pa2;
        }
        __syncthreads();

        float a0 = 0.f, a1 = 0.f, a2 = 0.f;
#pragma unroll
        for (int w = 0; w < NWARP; w++) {      // broadcast reads, conflict-free
            a0 += red[buf][w][0];
            a1 += red[buf][w][1];
            a2 += red[buf][w][2];
        }

        // scalar alpha recurrence
        float al = 1.f + a0;
        al += fmaf(al, a1, d01);
        al += fmaf(al, a2, d2);

        // out = alpha * x + (b0+b1+b2)
        float4 o;
        o.x = fmaf(al, xv.x, bsum.x);
        o.y = fmaf(al, xv.y, bsum.y);
        o.z = fmaf(al, xv.z, bsum.z);
        o.w = fmaf(al, xv.w, bsum.w);
        __stcs(op + (size_t)r * F4, o);

        xv = xnext;
    }
}

extern "C" void kernel_launch(void* const* d_in, const int* in_sizes, int n_in,
                              void* d_out, int out_size)
{
    const float* x    = (const float*)d_in[0];   // (B, D, 1)
    const float* W    = (const float*)d_in[1];   // (L, D, 1)
    const float* bias = (const float*)d_in[2];   // (L, D, 1)
    float* out = (float*)d_out;

    const int B = in_sizes[0] / D;               // 16384
    cross_layer_kernel<<<B / R, THREADS>>>(x, W, bias, out);
}

// round 5
// speedup vs baseline: 1.3355x; 1.3355x over previous
#include <cuda_runtime.h>

// DCN cross layer, L=3, D=1024, B=16384 — algebraic form.
//   a_l  = dot(x, W_l)  (3 independent dots)
//   d_ml = dot(bias_m, W_l)  (batch-independent, once per CTA)
//   alpha recurrence, out = alpha*x + (b0+b1+b2)
// One warp per TWO rows, processed concurrently: every smem W/Bs load is
// shared between both rows (halves L1/smem traffic vs R3) and the warp keeps
// 16 x-loads in flight (double the memory-level parallelism).
// NO barriers in the row path.

static constexpr int D  = 1024;
static constexpr int F4 = D / 4;            // 256 float4 per row
static constexpr int THREADS = 256;
static constexpr int NWARP = THREADS / 32;  // 8
static constexpr int ROWS_PER_CTA = NWARP * 2;   // 16

__device__ __forceinline__ float dot4(float4 a, float4 b) {
    return fmaf(a.x, b.x, fmaf(a.y, b.y, fmaf(a.z, b.z, a.w * b.w)));
}
__device__ __forceinline__ float wred(float v) {
#pragma unroll
    for (int o = 16; o > 0; o >>= 1)
        v += __shfl_xor_sync(0xffffffffu, v, o);
    return v;
}

__global__ __launch_bounds__(THREADS, 2)
void cross_layer_kernel(const float* __restrict__ x,
                        const float* __restrict__ W,
                        const float* __restrict__ bias,
                        float* __restrict__ out)
{
    __shared__ float4 Ws[3][F4];
    __shared__ float4 Bs[F4];               // b0+b1+b2
    __shared__ float  dred[NWARP][3];

    const int t    = threadIdx.x;
    const int warp = t >> 5;
    const int lane = t & 31;

    // ---- prologue (once per CTA): smem fill + d-constants ----
    const float4* W4 = reinterpret_cast<const float4*>(W);
    const float4* B4 = reinterpret_cast<const float4*>(bias);
    float4 w1 = W4[F4 + t];
    float4 w2 = W4[2 * F4 + t];
    Ws[0][t] = W4[t];
    Ws[1][t] = w1;
    Ws[2][t] = w2;
    float4 b0 = B4[t], b1 = B4[F4 + t], b2 = B4[2 * F4 + t];
    float4 bs;
    bs.x = b0.x + b1.x + b2.x;  bs.y = b0.y + b1.y + b2.y;
    bs.z = b0.z + b1.z + b2.z;  bs.w = b0.w + b1.w + b2.w;
    Bs[t] = bs;

    float p01 = wred(dot4(b0, w1));
    float p02 = wred(dot4(b0, w2));
    float p12 = wred(dot4(b1, w2));
    if (lane == 0) { dred[warp][0] = p01; dred[warp][1] = p02; dred[warp][2] = p12; }
    __syncthreads();

    float d01 = 0.f, d2 = 0.f;
#pragma unroll
    for (int w = 0; w < NWARP; w++) {
        d01 += dred[w][0];
        d2  += dred[w][1] + dred[w][2];      // d02 + d12
    }

    // ---- two rows per warp, fully independent, no barriers ----
    const size_t rowA = (size_t)blockIdx.x * ROWS_PER_CTA + warp * 2;
    const float4* xra = reinterpret_cast<const float4*>(x) + rowA * F4;
    const float4* xrb = xra + F4;
    float4* ora = reinterpret_cast<float4*>(out) + rowA * F4;
    float4* orb = ora + F4;

    float4 xa[8], xb[8];
#pragma unroll
    for (int j = 0; j < 8; j++) xa[j] = __ldcs(xra + lane + 32 * j);
#pragma unroll
    for (int j = 0; j < 8; j++) xb[j] = __ldcs(xrb + lane + 32 * j);

    // 6 dots (3 per row) — each W load feeds both rows
    float a0 = 0.f, a1 = 0.f, a2 = 0.f;
    float c0 = 0.f, c1 = 0.f, c2 = 0.f;
#pragma unroll
    for (int j = 0; j < 8; j++) {
        const int idx = lane + 32 * j;
        float4 q0 = Ws[0][idx], q1 = Ws[1][idx], q2 = Ws[2][idx];
        a0 = fmaf(xa[j].x, q0.x, fmaf(xa[j].y, q0.y, fmaf(xa[j].z, q0.z, fmaf(xa[j].w, q0.w, a0))));
        c0 = fmaf(xb[j].x, q0.x, fmaf(xb[j].y, q0.y, fmaf(xb[j].z, q0.z, fmaf(xb[j].w, q0.w, c0))));
        a1 = fmaf(xa[j].x, q1.x, fmaf(xa[j].y, q1.y, fmaf(xa[j].z, q1.z, fmaf(xa[j].w, q1.w, a1))));
        c1 = fmaf(xb[j].x, q1.x, fmaf(xb[j].y, q1.y, fmaf(xb[j].z, q1.z, fmaf(xb[j].w, q1.w, c1))));
        a2 = fmaf(xa[j].x, q2.x, fmaf(xa[j].y, q2.y, fmaf(xa[j].z, q2.z, fmaf(xa[j].w, q2.w, a2))));
        c2 = fmaf(xb[j].x, q2.x, fmaf(xb[j].y, q2.y, fmaf(xb[j].z, q2.z, fmaf(xb[j].w, q2.w, c2))));
    }
    a0 = wred(a0); a1 = wred(a1); a2 = wred(a2);
    c0 = wred(c0); c1 = wred(c1); c2 = wred(c2);

    // scalar alpha recurrences
    float ala = 1.f + a0;
    ala += fmaf(ala, a1, d01);
    ala += fmaf(ala, a2, d2);
    float alb = 1.f + c0;
    alb += fmaf(alb, c1, d01);
    alb += fmaf(alb, c2, d2);

    // out = alpha * x + bsum — Bs load shared between rows
#pragma unroll
    for (int j = 0; j < 8; j++) {
        const int idx = lane + 32 * j;
        float4 c = Bs[idx];
        float4 oa, ob;
        oa.x = fmaf(ala, xa[j].x, c.x);  ob.x = fmaf(alb, xb[j].x, c.x);
        oa.y = fmaf(ala, xa[j].y, c.y);  ob.y = fmaf(alb, xb[j].y, c.y);
        oa.z = fmaf(ala, xa[j].z, c.z);  ob.z = fmaf(alb, xb[j].z, c.z);
        oa.w = fmaf(ala, xa[j].w, c.w);  ob.w = fmaf(alb, xb[j].w, c.w);
        __stcs(ora + idx, oa);
        __stcs(orb + idx, ob);
    }
}

extern "C" void kernel_launch(void* const* d_in, const int* in_sizes, int n_in,
                              void* d_out, int out_size)
{
    const float* x    = (const float*)d_in[0];   // (B, D, 1)
    const float* W    = (const float*)d_in[1];   // (L, D, 1)
    const float* bias = (const float*)d_in[2];   // (L, D, 1)
    float* out = (float*)d_out;

    const int B = in_sizes[0] / D;               // 16384
    cross_layer_kernel<<<B / ROWS_PER_CTA, THREADS>>>(x, W, bias, out);
}